// round 2
// baseline (speedup 1.0000x reference)
#include <cuda_runtime.h>
#include <math.h>

#define NNODES 16384
#define HID 64
#define NEDGES 524288
#define UNITS 256

// scratch: two [N,64] fp32 buffers (4 MB each)
__device__ float g_tmp[NNODES * HID];
__device__ float g_h[NNODES * HID];

// ---------------------------------------------------------------------------
// C[M,64] = act(A[M,K] @ B[K,64] + bias)
// ACT: 0 = none, 1 = sigmoid.  M must be multiple of 128, K multiple of 32.
// ---------------------------------------------------------------------------
template <int ACT, bool HAS_BIAS>
__global__ __launch_bounds__(256, 2)
void gemm_n64(const float* __restrict__ A, const float* __restrict__ B,
              const float* __restrict__ bias, float* __restrict__ C, int K) {
    const int BM = 128, BK = 32;
    __shared__ float Asm[BK][BM + 4];   // transposed A tile, padded
    __shared__ float Bsm[BK][64];

    const int tid  = threadIdx.x;
    const int tcol = tid & 15;          // 16 col-groups of 4
    const int trow = tid >> 4;          // 16 row-groups of 8
    const int m0   = blockIdx.x * BM;

    float acc[8][4];
#pragma unroll
    for (int r = 0; r < 8; r++)
#pragma unroll
        for (int c = 0; c < 4; c++) acc[r][c] = 0.0f;

    const int lrow = tid >> 3;          // 0..31 (A load)
    const int lk4  = tid & 7;           // 0..7
    const int brow = tid >> 4;          // 0..15 (B load)
    const int bc4  = tid & 15;

    const int nchunk = K / BK;
    for (int ch = 0; ch < nchunk; ++ch) {
        const int k0 = ch * BK;
        // --- load A tile (transposed store into smem) ---
#pragma unroll
        for (int i = 0; i < 4; i++) {
            int r = lrow + 32 * i;
            float4 v = *(const float4*)&A[(size_t)(m0 + r) * K + k0 + lk4 * 4];
            Asm[lk4 * 4 + 0][r] = v.x;
            Asm[lk4 * 4 + 1][r] = v.y;
            Asm[lk4 * 4 + 2][r] = v.z;
            Asm[lk4 * 4 + 3][r] = v.w;
        }
        // --- load B tile ---
#pragma unroll
        for (int i = 0; i < 2; i++) {
            int r = brow + 16 * i;
            *(float4*)&Bsm[r][bc4 * 4] =
                *(const float4*)&B[(size_t)(k0 + r) * 64 + bc4 * 4];
        }
        __syncthreads();
        // --- compute ---
#pragma unroll
        for (int k = 0; k < BK; k++) {
            float4 a0 = *(const float4*)&Asm[k][trow * 8];
            float4 a1 = *(const float4*)&Asm[k][trow * 8 + 4];
            float4 b  = *(const float4*)&Bsm[k][tcol * 4];
            float ar[8] = {a0.x, a0.y, a0.z, a0.w, a1.x, a1.y, a1.z, a1.w};
            float br[4] = {b.x, b.y, b.z, b.w};
#pragma unroll
            for (int r = 0; r < 8; r++)
#pragma unroll
                for (int c = 0; c < 4; c++) acc[r][c] = fmaf(ar[r], br[c], acc[r][c]);
        }
        __syncthreads();
    }

    // --- epilogue ---
    float bv[4] = {0.f, 0.f, 0.f, 0.f};
    if (HAS_BIAS) {
#pragma unroll
        for (int c = 0; c < 4; c++) bv[c] = bias[tcol * 4 + c];
    }
#pragma unroll
    for (int r = 0; r < 8; r++) {
        float4 o;
        float* po = &o.x;
#pragma unroll
        for (int c = 0; c < 4; c++) {
            float v = acc[r][c] + bv[c];
            if (ACT == 1) v = 1.0f / (1.0f + expf(-v));
            po[c] = v;
        }
        *(float4*)&C[(size_t)(m0 + trow * 8 + r) * 64 + tcol * 4] = o;
    }
}

// ---------------------------------------------------------------------------
// Fused edge pipeline: gather -> relu(ES @ Wd + bd) -> softmax(@Wo + bo) * mask
// 64 edges per CTA, 256 threads. Never materializes edge_state or d in HBM.
// ---------------------------------------------------------------------------
__global__ __launch_bounds__(256, 2)
void edge_kernel(const float* __restrict__ h, const int* __restrict__ edges,
                 const int* __restrict__ mask,
                 const float* __restrict__ Wd, const float* __restrict__ bd,
                 const float* __restrict__ Wo, const float* __restrict__ bo,
                 float* __restrict__ out) {
    const int BM = 64, BK = 32;
    __shared__ float ESm[BK][BM + 4];    // [k][edge], transposed
    __shared__ float Wdsm[BK][UNITS];    // 32 KB

    const int tid  = threadIdx.x;
    const int lane = tid & 31;           // unit group: units lane*8 .. lane*8+7
    const int wrp  = tid >> 5;           // 8 warps; edges wrp*8 .. wrp*8+7
    const int e0   = blockIdx.x * BM;

    float acc[8][8];                     // [edge][unit]
#pragma unroll
    for (int r = 0; r < 8; r++)
#pragma unroll
        for (int u = 0; u < 8; u++) acc[r][u] = 0.0f;

    const int le = tid >> 3;             // 0..31 (ES load)
    const int lf = tid & 7;              // 0..7
    const int lr = tid >> 6;             // 0..3  (Wd load)
    const int lc = tid & 63;             // 0..63

    for (int ch = 0; ch < 4; ch++) {
        const int sel   = ch >> 1;       // 0 = src endpoint, 1 = dst endpoint
        const int hcol0 = (ch & 1) * 32; // column within h row
        // --- gather edge_state chunk, transposed into smem ---
#pragma unroll
        for (int i = 0; i < 2; i++) {
            int e = le + 32 * i;
            int node = edges[2 * (e0 + e) + sel];
            float4 v = *(const float4*)&h[(size_t)node * 64 + hcol0 + lf * 4];
            ESm[lf * 4 + 0][e] = v.x;
            ESm[lf * 4 + 1][e] = v.y;
            ESm[lf * 4 + 2][e] = v.z;
            ESm[lf * 4 + 3][e] = v.w;
        }
        // --- load Wd tile rows ch*32 .. ch*32+31 ---
#pragma unroll
        for (int i = 0; i < 8; i++) {
            int r = lr + 4 * i;
            *(float4*)&Wdsm[r][lc * 4] =
                *(const float4*)&Wd[(size_t)(ch * 32 + r) * UNITS + lc * 4];
        }
        __syncthreads();
        // --- compute ---
#pragma unroll
        for (int k = 0; k < BK; k++) {
            float4 ea = *(const float4*)&ESm[k][wrp * 8];      // broadcast across warp
            float4 eb = *(const float4*)&ESm[k][wrp * 8 + 4];
            float4 w0 = *(const float4*)&Wdsm[k][lane * 8];
            float4 w1 = *(const float4*)&Wdsm[k][lane * 8 + 4];
            float er[8] = {ea.x, ea.y, ea.z, ea.w, eb.x, eb.y, eb.z, eb.w};
            float wr[8] = {w0.x, w0.y, w0.z, w0.w, w1.x, w1.y, w1.z, w1.w};
#pragma unroll
            for (int r = 0; r < 8; r++)
#pragma unroll
                for (int u = 0; u < 8; u++) acc[r][u] = fmaf(er[r], wr[u], acc[r][u]);
        }
        __syncthreads();
    }

    // --- epilogue: d = relu(acc + bd); partial out = d @ Wo (per-lane) ---
    float p0[8], p1[8];
#pragma unroll
    for (int r = 0; r < 8; r++) { p0[r] = 0.0f; p1[r] = 0.0f; }
#pragma unroll
    for (int u = 0; u < 8; u++) {
        int uu = lane * 8 + u;
        float b  = bd[uu];
        float w0 = Wo[uu * 2 + 0];
        float w1 = Wo[uu * 2 + 1];
#pragma unroll
        for (int r = 0; r < 8; r++) {
            float d = fmaxf(acc[r][u] + b, 0.0f);
            p0[r] = fmaf(d, w0, p0[r]);
            p1[r] = fmaf(d, w1, p1[r]);
        }
    }
    // --- butterfly reduce across the 32 lanes (all share the same 8 edges) ---
#pragma unroll
    for (int off = 16; off > 0; off >>= 1) {
#pragma unroll
        for (int r = 0; r < 8; r++) {
            p0[r] += __shfl_xor_sync(0xffffffffu, p0[r], off);
            p1[r] += __shfl_xor_sync(0xffffffffu, p1[r], off);
        }
    }
    // lanes 0..7 finalize one edge each
    if (lane < 8) {
        int r = lane;
        int e = e0 + wrp * 8 + r;
        float v0 = p0[r] + bo[0];
        float v1 = p1[r] + bo[1];
        float m  = fmaxf(v0, v1);
        float x0 = expf(v0 - m);
        float x1 = expf(v1 - m);
        float inv = 1.0f / (x0 + x1);
        float mk = (float)mask[e];
        out[2 * e + 0] = x0 * inv * mk;
        out[2 * e + 1] = x1 * inv * mk;
    }
}

// ---------------------------------------------------------------------------
extern "C" void kernel_launch(void* const* d_in, const int* in_sizes, int n_in,
                              void* d_out, int out_size) {
    const float* X     = (const float*)d_in[0];   // node_state [N,128]
    const float* Adj   = (const float*)d_in[1];   // adjacency [N,N]
    const int*   edges = (const int*)d_in[2];     // out_edges [E,2]
    const int*   smask = (const int*)d_in[3];     // set_mask [E,1]
    const float* W1    = (const float*)d_in[4];
    const float* b1    = (const float*)d_in[5];
    const float* W2    = (const float*)d_in[6];
    const float* b2    = (const float*)d_in[7];
    const float* Wd    = (const float*)d_in[8];
    const float* bd    = (const float*)d_in[9];
    const float* Wo    = (const float*)d_in[10];
    const float* bo    = (const float*)d_in[11];
    float* out = (float*)d_out;

    float *tmp, *h;
    cudaGetSymbolAddress((void**)&tmp, g_tmp);
    cudaGetSymbolAddress((void**)&h, g_h);

    const int GRID = NNODES / 128;  // 128 CTAs

    // tmp = X @ W1
    gemm_n64<0, false><<<GRID, 256>>>(X, W1, nullptr, tmp, 128);
    // h = sigmoid(A @ tmp + b1)
    gemm_n64<1, true><<<GRID, 256>>>(Adj, tmp, b1, h, NNODES);
    // tmp = h @ W2
    gemm_n64<0, false><<<GRID, 256>>>(h, W2, nullptr, tmp, 64);
    // h = sigmoid(A @ tmp + b2)
    gemm_n64<1, true><<<GRID, 256>>>(Adj, tmp, b2, h, NNODES);
    // fused edge MLP + softmax + mask
    edge_kernel<<<NEDGES / 64, 256>>>(h, edges, smask, Wd, bd, Wo, bo, out);
}

// round 4
// speedup vs baseline: 2.1103x; 2.1103x over previous
#include <cuda_runtime.h>
#include <math.h>
#include <stdint.h>

#define NNODES 16384
#define HID 64
#define NEDGES 524288
#define UNITS 256

// scratch buffers
__device__ float g_tmp[NNODES * HID];      // [N,64]  (B operand for adj_mma, tf32-rounded)
__device__ float g_h[NNODES * HID];        // [N,64]

// ===========================================================================
// helpers
// ===========================================================================
__device__ __forceinline__ uint32_t smem_u32(const void* p) {
    uint32_t a;
    asm("{ .reg .u64 t; cvta.to.shared.u64 t, %1; cvt.u32.u64 %0, t; }"
        : "=r"(a) : "l"(p));
    return a;
}
__device__ __forceinline__ void cp_async16(uint32_t dst, const void* src) {
    asm volatile("cp.async.cg.shared.global [%0], [%1], 16;" :: "r"(dst), "l"(src));
}
__device__ __forceinline__ void cp_commit() {
    asm volatile("cp.async.commit_group;" ::: "memory");
}
__device__ __forceinline__ float ftf(float x) {   // round fp32 -> tf32 (rna)
    uint32_t u;
    asm("cvt.rna.tf32.f32 %0, %1;" : "=r"(u) : "f"(x));
    return __uint_as_float(u);
}
__device__ __forceinline__ void mma8(float* d, const float* a, const float* b) {
    asm volatile(
        "mma.sync.aligned.m16n8k8.row.col.f32.tf32.tf32.f32 "
        "{%0,%1,%2,%3}, {%4,%5,%6,%7}, {%8,%9}, {%0,%1,%2,%3};"
        : "+f"(d[0]), "+f"(d[1]), "+f"(d[2]), "+f"(d[3])
        : "r"(__float_as_uint(a[0])), "r"(__float_as_uint(a[1])),
          "r"(__float_as_uint(a[2])), "r"(__float_as_uint(a[3])),
          "r"(__float_as_uint(b[0])), "r"(__float_as_uint(b[1])));
}

// ===========================================================================
// adj_mma: C[N,64] = sigmoid(A[N,N] @ B[N,64] + bias), tf32 mma.sync
// BM=128, BN=64, BK=32. 8 warps (4x2), warp tile 32x32. 3-stage cp.async.
// smem: A stride 36 floats (banks 4r+c, conflict-free),
//       B stride 72 floats (banks 8k+n, conflict-free). 16B-aligned rows.
// ===========================================================================
#define NITK (NNODES / 32)          // 512
#define A_STRIDE 36
#define B_STRIDE 72
#define STAGE_FLOATS (128 * A_STRIDE + 32 * B_STRIDE)   // 4608 + 2304 = 6912
#define SMEM_DYN (3 * STAGE_FLOATS * 4)                 // 82944 B

__global__ __launch_bounds__(256, 1)
void adj_mma(const float* __restrict__ A, const float* __restrict__ B,
             const float* __restrict__ bias, float* __restrict__ C) {
    extern __shared__ float dsm[];
    const int tid = threadIdx.x;
    const int lane = tid & 31, wid = tid >> 5;
    const int wm = wid >> 1, wn = wid & 1;      // 4x2 warp grid
    const int gr = lane >> 2, tg = lane & 3;
    const int m0 = blockIdx.x * 128;

    float acc[2][4][4];
#pragma unroll
    for (int mf = 0; mf < 2; mf++)
#pragma unroll
        for (int nf = 0; nf < 4; nf++)
#pragma unroll
            for (int q = 0; q < 4; q++) acc[mf][nf][q] = 0.0f;

    // ---- tile loader: one cp.async group per call ----
    auto load_tile = [&](int stage, int kt) {
        float* As = dsm + stage * STAGE_FLOATS;
        float* Bs = As + 128 * A_STRIDE;
        const int k0 = kt * 32;
#pragma unroll
        for (int i = 0; i < 4; i++) {           // A: 128x32 = 1024 granules
            int g = tid + i * 256;
            int r = g >> 3, c = g & 7;
            cp_async16(smem_u32(As + r * A_STRIDE + c * 4),
                       A + (size_t)(m0 + r) * NNODES + k0 + c * 4);
        }
#pragma unroll
        for (int i = 0; i < 2; i++) {           // B: 32x64 = 512 granules
            int g = tid + i * 256;
            int r = g >> 4, c = g & 15;
            cp_async16(smem_u32(Bs + r * B_STRIDE + c * 4),
                       B + (size_t)(k0 + r) * 64 + c * 4);
        }
        cp_commit();
    };

    load_tile(0, 0);
    load_tile(1, 1);

    for (int it = 0; it < NITK; ++it) {
        const int s = it % 3;
        asm volatile("cp.async.wait_group 1;" ::: "memory");
        __syncthreads();                        // data(it) ready, stage reuse safe
        if (it + 2 < NITK) load_tile((it + 2) % 3, it + 2);
        else cp_commit();                       // empty group keeps wait_group math exact

        const float* As = dsm + s * STAGE_FLOATS;
        const float* Bs = As + 128 * A_STRIDE;

#pragma unroll
        for (int ks = 0; ks < 4; ++ks) {
            float a[2][4], b[4][2];
#pragma unroll
            for (int mf = 0; mf < 2; mf++) {
                const int r0 = wm * 32 + mf * 16 + gr;
                const int kc = ks * 8 + tg;
                a[mf][0] = ftf(As[r0 * A_STRIDE + kc]);
                a[mf][1] = ftf(As[(r0 + 8) * A_STRIDE + kc]);
                a[mf][2] = ftf(As[r0 * A_STRIDE + kc + 4]);
                a[mf][3] = ftf(As[(r0 + 8) * A_STRIDE + kc + 4]);
            }
#pragma unroll
            for (int nf = 0; nf < 4; nf++) {
                const int c0 = wn * 32 + nf * 8 + gr;
                const int kc = ks * 8 + tg;
                b[nf][0] = Bs[kc * B_STRIDE + c0];          // B pre-rounded to tf32
                b[nf][1] = Bs[(kc + 4) * B_STRIDE + c0];
            }
#pragma unroll
            for (int mf = 0; mf < 2; mf++)
#pragma unroll
                for (int nf = 0; nf < 4; nf++)
                    mma8(acc[mf][nf], a[mf], b[nf]);
        }
    }

    // ---- epilogue: bias + sigmoid, write C ----
#pragma unroll
    for (int mf = 0; mf < 2; mf++) {
#pragma unroll
        for (int nf = 0; nf < 4; nf++) {
            const int row = m0 + wm * 32 + mf * 16 + gr;
            const int col = wn * 32 + nf * 8 + 2 * tg;
            const float b0 = bias[col], b1 = bias[col + 1];
            float v0 = acc[mf][nf][0] + b0, v1 = acc[mf][nf][1] + b1;
            float v2 = acc[mf][nf][2] + b0, v3 = acc[mf][nf][3] + b1;
            float2 o0 = make_float2(1.0f / (1.0f + expf(-v0)), 1.0f / (1.0f + expf(-v1)));
            float2 o1 = make_float2(1.0f / (1.0f + expf(-v2)), 1.0f / (1.0f + expf(-v3)));
            *(float2*)&C[(size_t)row * 64 + col] = o0;
            *(float2*)&C[(size_t)(row + 8) * 64 + col] = o1;
        }
    }
}

// ===========================================================================
// gemm_n64 (SIMT): C[M,64] = A[M,K] @ B[K,64], output rounded to tf32.
// Small K only (128 / 64); ~0.3 GFLOP total, negligible.
// ===========================================================================
__global__ __launch_bounds__(256, 2)
void gemm_n64(const float* __restrict__ A, const float* __restrict__ B,
              float* __restrict__ C, int K) {
    const int BM = 128, BK = 32;
    __shared__ float Asm[BK][BM + 4];
    __shared__ float Bsm[BK][64];

    const int tid = threadIdx.x;
    const int tcol = tid & 15;
    const int trow = tid >> 4;
    const int m0 = blockIdx.x * BM;

    float acc[8][4];
#pragma unroll
    for (int r = 0; r < 8; r++)
#pragma unroll
        for (int c = 0; c < 4; c++) acc[r][c] = 0.0f;

    const int lrow = tid >> 3;
    const int lk4 = tid & 7;
    const int brow = tid >> 4;
    const int bc4 = tid & 15;

    const int nchunk = K / BK;
    for (int ch = 0; ch < nchunk; ++ch) {
        const int k0 = ch * BK;
#pragma unroll
        for (int i = 0; i < 4; i++) {
            int r = lrow + 32 * i;
            float4 v = *(const float4*)&A[(size_t)(m0 + r) * K + k0 + lk4 * 4];
            Asm[lk4 * 4 + 0][r] = v.x;
            Asm[lk4 * 4 + 1][r] = v.y;
            Asm[lk4 * 4 + 2][r] = v.z;
            Asm[lk4 * 4 + 3][r] = v.w;
        }
#pragma unroll
        for (int i = 0; i < 2; i++) {
            int r = brow + 16 * i;
            *(float4*)&Bsm[r][bc4 * 4] = *(const float4*)&B[(size_t)(k0 + r) * 64 + bc4 * 4];
        }
        __syncthreads();
#pragma unroll
        for (int k = 0; k < BK; k++) {
            float4 a0 = *(const float4*)&Asm[k][trow * 8];
            float4 a1 = *(const float4*)&Asm[k][trow * 8 + 4];
            float4 b = *(const float4*)&Bsm[k][tcol * 4];
            float ar[8] = {a0.x, a0.y, a0.z, a0.w, a1.x, a1.y, a1.z, a1.w};
            float br[4] = {b.x, b.y, b.z, b.w};
#pragma unroll
            for (int r = 0; r < 8; r++)
#pragma unroll
                for (int c = 0; c < 4; c++) acc[r][c] = fmaf(ar[r], br[c], acc[r][c]);
        }
        __syncthreads();
    }
#pragma unroll
    for (int r = 0; r < 8; r++) {
        float4 o = make_float4(ftf(acc[r][0]), ftf(acc[r][1]), ftf(acc[r][2]), ftf(acc[r][3]));
        *(float4*)&C[(size_t)(m0 + trow * 8 + r) * 64 + tcol * 4] = o;
    }
}

// ===========================================================================
// Fused edge pipeline (unchanged from R2)
// ===========================================================================
__global__ __launch_bounds__(256, 2)
void edge_kernel(const float* __restrict__ h, const int* __restrict__ edges,
                 const int* __restrict__ mask,
                 const float* __restrict__ Wd, const float* __restrict__ bd,
                 const float* __restrict__ Wo, const float* __restrict__ bo,
                 float* __restrict__ out) {
    const int BM = 64, BK = 32;
    __shared__ float ESm[BK][BM + 4];
    __shared__ float Wdsm[BK][UNITS];

    const int tid = threadIdx.x;
    const int lane = tid & 31;
    const int wrp = tid >> 5;
    const int e0 = blockIdx.x * BM;

    float acc[8][8];
#pragma unroll
    for (int r = 0; r < 8; r++)
#pragma unroll
        for (int u = 0; u < 8; u++) acc[r][u] = 0.0f;

    const int le = tid >> 3;
    const int lf = tid & 7;
    const int lr = tid >> 6;
    const int lc = tid & 63;

    for (int ch = 0; ch < 4; ch++) {
        const int sel = ch >> 1;
        const int hcol0 = (ch & 1) * 32;
#pragma unroll
        for (int i = 0; i < 2; i++) {
            int e = le + 32 * i;
            int node = edges[2 * (e0 + e) + sel];
            float4 v = *(const float4*)&h[(size_t)node * 64 + hcol0 + lf * 4];
            ESm[lf * 4 + 0][e] = v.x;
            ESm[lf * 4 + 1][e] = v.y;
            ESm[lf * 4 + 2][e] = v.z;
            ESm[lf * 4 + 3][e] = v.w;
        }
#pragma unroll
        for (int i = 0; i < 8; i++) {
            int r = lr + 4 * i;
            *(float4*)&Wdsm[r][lc * 4] =
                *(const float4*)&Wd[(size_t)(ch * 32 + r) * UNITS + lc * 4];
        }
        __syncthreads();
#pragma unroll
        for (int k = 0; k < BK; k++) {
            float4 ea = *(const float4*)&ESm[k][wrp * 8];
            float4 eb = *(const float4*)&ESm[k][wrp * 8 + 4];
            float4 w0 = *(const float4*)&Wdsm[k][lane * 8];
            float4 w1 = *(const float4*)&Wdsm[k][lane * 8 + 4];
            float er[8] = {ea.x, ea.y, ea.z, ea.w, eb.x, eb.y, eb.z, eb.w};
            float wr[8] = {w0.x, w0.y, w0.z, w0.w, w1.x, w1.y, w1.z, w1.w};
#pragma unroll
            for (int r = 0; r < 8; r++)
#pragma unroll
                for (int u = 0; u < 8; u++) acc[r][u] = fmaf(er[r], wr[u], acc[r][u]);
        }
        __syncthreads();
    }

    float p0[8], p1[8];
#pragma unroll
    for (int r = 0; r < 8; r++) { p0[r] = 0.0f; p1[r] = 0.0f; }
#pragma unroll
    for (int u = 0; u < 8; u++) {
        int uu = lane * 8 + u;
        float b = bd[uu];
        float w0 = Wo[uu * 2 + 0];
        float w1 = Wo[uu * 2 + 1];
#pragma unroll
        for (int r = 0; r < 8; r++) {
            float d = fmaxf(acc[r][u] + b, 0.0f);
            p0[r] = fmaf(d, w0, p0[r]);
            p1[r] = fmaf(d, w1, p1[r]);
        }
    }
#pragma unroll
    for (int off = 16; off > 0; off >>= 1) {
#pragma unroll
        for (int r = 0; r < 8; r++) {
            p0[r] += __shfl_xor_sync(0xffffffffu, p0[r], off);
            p1[r] += __shfl_xor_sync(0xffffffffu, p1[r], off);
        }
    }
    if (lane < 8) {
        int r = lane;
        int e = e0 + wrp * 8 + r;
        float v0 = p0[r] + bo[0];
        float v1 = p1[r] + bo[1];
        float m = fmaxf(v0, v1);
        float x0 = expf(v0 - m);
        float x1 = expf(v1 - m);
        float inv = 1.0f / (x0 + x1);
        float mk = (float)mask[e];
        out[2 * e + 0] = x0 * inv * mk;
        out[2 * e + 1] = x1 * inv * mk;
    }
}

// ===========================================================================
extern "C" void kernel_launch(void* const* d_in, const int* in_sizes, int n_in,
                              void* d_out, int out_size) {
    const float* X     = (const float*)d_in[0];
    const float* Adj   = (const float*)d_in[1];
    const int*   edges = (const int*)d_in[2];
    const int*   smask = (const int*)d_in[3];
    const float* W1    = (const float*)d_in[4];
    const float* b1    = (const float*)d_in[5];
    const float* W2    = (const float*)d_in[6];
    const float* b2    = (const float*)d_in[7];
    const float* Wd    = (const float*)d_in[8];
    const float* bd    = (const float*)d_in[9];
    const float* Wo    = (const float*)d_in[10];
    const float* bo    = (const float*)d_in[11];
    float* out = (float*)d_out;

    float *tmp, *h;
    cudaGetSymbolAddress((void**)&tmp, g_tmp);
    cudaGetSymbolAddress((void**)&h, g_h);

    cudaFuncSetAttribute(adj_mma, cudaFuncAttributeMaxDynamicSharedMemorySize, SMEM_DYN);

    // layer 1
    gemm_n64<<<NNODES / 128, 256>>>(X, W1, tmp, 128);
    adj_mma<<<NNODES / 128, 256, SMEM_DYN>>>(Adj, tmp, b1, h);
    // layer 2
    gemm_n64<<<NNODES / 128, 256>>>(h, W2, tmp, 64);
    adj_mma<<<NNODES / 128, 256, SMEM_DYN>>>(Adj, tmp, b2, h);
    // fused edge MLP
    edge_kernel<<<NEDGES / 64, 256>>>(h, edges, smask, Wd, bd, Wo, bo, out);
}

// round 5
// speedup vs baseline: 3.2458x; 1.5380x over previous
#include <cuda_runtime.h>
#include <math.h>
#include <stdint.h>

#define NNODES 16384
#define HID 64
#define NEDGES 524288
#define UNITS 256

// scratch buffers
__device__ float g_tmp[NNODES * HID];      // [N,64]  (B operand for adj_mma, tf32-rounded)
__device__ float g_h[NNODES * HID];        // [N,64]

// ===========================================================================
// helpers
// ===========================================================================
__device__ __forceinline__ uint32_t smem_u32(const void* p) {
    uint32_t a;
    asm("{ .reg .u64 t; cvta.to.shared.u64 t, %1; cvt.u32.u64 %0, t; }"
        : "=r"(a) : "l"(p));
    return a;
}
__device__ __forceinline__ void cp_async16(uint32_t dst, const void* src) {
    asm volatile("cp.async.cg.shared.global [%0], [%1], 16;" :: "r"(dst), "l"(src));
}
__device__ __forceinline__ void cp_commit() {
    asm volatile("cp.async.commit_group;" ::: "memory");
}
__device__ __forceinline__ float ftf(float x) {   // round fp32 -> tf32 (rna)
    uint32_t u;
    asm("cvt.rna.tf32.f32 %0, %1;" : "=r"(u) : "f"(x));
    return __uint_as_float(u);
}
__device__ __forceinline__ void mma8(float* d, const float* a, const float* b) {
    asm volatile(
        "mma.sync.aligned.m16n8k8.row.col.f32.tf32.tf32.f32 "
        "{%0,%1,%2,%3}, {%4,%5,%6,%7}, {%8,%9}, {%0,%1,%2,%3};"
        : "+f"(d[0]), "+f"(d[1]), "+f"(d[2]), "+f"(d[3])
        : "r"(__float_as_uint(a[0])), "r"(__float_as_uint(a[1])),
          "r"(__float_as_uint(a[2])), "r"(__float_as_uint(a[3])),
          "r"(__float_as_uint(b[0])), "r"(__float_as_uint(b[1])));
}

// ===========================================================================
// adj_mma: C[N,64] = sigmoid(A[N,N] @ B[N,64] + bias), tf32 mma.sync
// BM=128, BN=64, BK=64. 8 warps (4x2), warp tile 32x32. 3-stage cp.async.
// A stride 68 floats, B stride 72 floats (both conflict-free fragment loads).
// ===========================================================================
#define BK2 64
#define NIT2 (NNODES / BK2)                 // 256
#define A_STRIDE 68
#define B_STRIDE 72
#define STAGE_FLOATS (128 * A_STRIDE + BK2 * B_STRIDE)  // 8704 + 4608 = 13312
#define SMEM_ADJ (3 * STAGE_FLOATS * 4)                 // 159744 B

__global__ __launch_bounds__(256, 1)
void adj_mma(const float* __restrict__ A, const float* __restrict__ B,
             const float* __restrict__ bias, float* __restrict__ C) {
    extern __shared__ float dsm[];
    const int tid = threadIdx.x;
    const int lane = tid & 31, wid = tid >> 5;
    const int wm = wid >> 1, wn = wid & 1;      // 4x2 warp grid
    const int gr = lane >> 2, tg = lane & 3;
    const int m0 = blockIdx.x * 128;

    float acc[2][4][4];
#pragma unroll
    for (int mf = 0; mf < 2; mf++)
#pragma unroll
        for (int nf = 0; nf < 4; nf++)
#pragma unroll
            for (int q = 0; q < 4; q++) acc[mf][nf][q] = 0.0f;

    auto load_tile = [&](int stage, int kt) {
        float* As = dsm + stage * STAGE_FLOATS;
        float* Bs = As + 128 * A_STRIDE;
        const int k0 = kt * BK2;
#pragma unroll
        for (int i = 0; i < 8; i++) {           // A: 128x64 = 2048 granules
            int g = tid + i * 256;
            int r = g >> 4, c = g & 15;
            cp_async16(smem_u32(As + r * A_STRIDE + c * 4),
                       A + (size_t)(m0 + r) * NNODES + k0 + c * 4);
        }
#pragma unroll
        for (int i = 0; i < 4; i++) {           // B: 64x64 = 1024 granules
            int g = tid + i * 256;
            int r = g >> 4, c = g & 15;
            cp_async16(smem_u32(Bs + r * B_STRIDE + c * 4),
                       B + (size_t)(k0 + r) * 64 + c * 4);
        }
        cp_commit();
    };

    load_tile(0, 0);
    load_tile(1, 1);

    for (int it = 0; it < NIT2; ++it) {
        const int s = it % 3;
        asm volatile("cp.async.wait_group 1;" ::: "memory");
        __syncthreads();
        if (it + 2 < NIT2) load_tile((it + 2) % 3, it + 2);
        else cp_commit();

        const float* As = dsm + s * STAGE_FLOATS;
        const float* Bs = As + 128 * A_STRIDE;

#pragma unroll
        for (int ks = 0; ks < 8; ++ks) {
            float a[2][4], b[4][2];
            const int kc = ks * 8 + tg;
#pragma unroll
            for (int mf = 0; mf < 2; mf++) {
                const int r0 = wm * 32 + mf * 16 + gr;
                a[mf][0] = ftf(As[r0 * A_STRIDE + kc]);
                a[mf][1] = ftf(As[(r0 + 8) * A_STRIDE + kc]);
                a[mf][2] = ftf(As[r0 * A_STRIDE + kc + 4]);
                a[mf][3] = ftf(As[(r0 + 8) * A_STRIDE + kc + 4]);
            }
#pragma unroll
            for (int nf = 0; nf < 4; nf++) {
                const int c0 = wn * 32 + nf * 8 + gr;
                b[nf][0] = Bs[kc * B_STRIDE + c0];      // B pre-rounded to tf32
                b[nf][1] = Bs[(kc + 4) * B_STRIDE + c0];
            }
#pragma unroll
            for (int mf = 0; mf < 2; mf++)
#pragma unroll
                for (int nf = 0; nf < 4; nf++)
                    mma8(acc[mf][nf], a[mf], b[nf]);
        }
    }

    // epilogue: bias + sigmoid
#pragma unroll
    for (int mf = 0; mf < 2; mf++) {
#pragma unroll
        for (int nf = 0; nf < 4; nf++) {
            const int row = m0 + wm * 32 + mf * 16 + gr;
            const int col = wn * 32 + nf * 8 + 2 * tg;
            const float b0 = bias[col], b1 = bias[col + 1];
            float v0 = acc[mf][nf][0] + b0, v1 = acc[mf][nf][1] + b1;
            float v2 = acc[mf][nf][2] + b0, v3 = acc[mf][nf][3] + b1;
            float2 o0 = make_float2(1.0f / (1.0f + expf(-v0)), 1.0f / (1.0f + expf(-v1)));
            float2 o1 = make_float2(1.0f / (1.0f + expf(-v2)), 1.0f / (1.0f + expf(-v3)));
            *(float2*)&C[(size_t)row * 64 + col] = o0;
            *(float2*)&C[(size_t)(row + 8) * 64 + col] = o1;
        }
    }
}

// ===========================================================================
// edge_mma: fused  relu(concat(h[src],h[dst]) @ Wd + bd) @ Wo -> softmax*mask
// BM=128 edges, BN=256 units, K=128 in 4 chunks of 32. 512 threads (4x4 warps,
// warp tile 32x64). Double-buffered cp.async. tf32 mma for the big GEMM; the
// tiny (256->2) contraction stays fp32 in registers.
// smem layout (floats): ES0[4608] ES1[4608] Wd0[8448] Wd1[8448] red[1024]
// ===========================================================================
#define ES_STRIDE 36
#define WD_STRIDE 264
#define ES_FLOATS (128 * ES_STRIDE)        // 4608
#define WD_FLOATS (32 * WD_STRIDE)         // 8448
#define OFF_ES0 0
#define OFF_ES1 ES_FLOATS
#define OFF_WD0 (2 * ES_FLOATS)
#define OFF_WD1 (2 * ES_FLOATS + WD_FLOATS)
#define OFF_RED (2 * ES_FLOATS + 2 * WD_FLOATS)
#define SMEM_EDGE ((OFF_RED + 4 * 128 * 2) * 4)   // 108544 B

__global__ __launch_bounds__(512, 1)
void edge_mma(const float* __restrict__ h, const int* __restrict__ edges,
              const int* __restrict__ mask,
              const float* __restrict__ Wd, const float* __restrict__ bd,
              const float* __restrict__ Wo, const float* __restrict__ bo,
              float* __restrict__ out) {
    extern __shared__ float dsm[];
    const int tid = threadIdx.x;
    const int lane = tid & 31, wid = tid >> 5;
    const int wm = wid >> 2, wn = wid & 3;      // 4x4 warp grid
    const int gr = lane >> 2, tg = lane & 3;
    const int e0 = blockIdx.x * 128;

    float acc[2][8][4];
#pragma unroll
    for (int mf = 0; mf < 2; mf++)
#pragma unroll
        for (int nf = 0; nf < 8; nf++)
#pragma unroll
            for (int q = 0; q < 4; q++) acc[mf][nf][q] = 0.0f;

    auto load_chunk = [&](int ch, int buf) {
        float* ESm = dsm + (buf ? OFF_ES1 : OFF_ES0);
        float* Wds = dsm + (buf ? OFF_WD1 : OFF_WD0);
        const int sel = ch >> 1, hcol0 = (ch & 1) * 32;
        // gather ES: 128 edges x 8 float4 = 1024 granules, 512 thr -> 2 each
#pragma unroll
        for (int i = 0; i < 2; i++) {
            int g = tid + i * 512;
            int e = g >> 3, c = g & 7;
            int node = __ldg(&edges[2 * (e0 + e) + sel]);
            cp_async16(smem_u32(ESm + e * ES_STRIDE + c * 4),
                       h + (size_t)node * 64 + hcol0 + c * 4);
        }
        // Wd rows ch*32..+31: 32x64 float4 = 2048 granules -> 4 each
#pragma unroll
        for (int i = 0; i < 4; i++) {
            int g = tid + i * 512;
            int r = g >> 6, c = g & 63;
            cp_async16(smem_u32(Wds + r * WD_STRIDE + c * 4),
                       Wd + (size_t)(ch * 32 + r) * UNITS + c * 4);
        }
        cp_commit();
    };

    load_chunk(0, 0);
    for (int ch = 0; ch < 4; ++ch) {
        if (ch + 1 < 4) load_chunk(ch + 1, (ch + 1) & 1);
        else cp_commit();
        asm volatile("cp.async.wait_group 1;" ::: "memory");
        __syncthreads();

        const float* ESm = dsm + ((ch & 1) ? OFF_ES1 : OFF_ES0);
        const float* Wds = dsm + ((ch & 1) ? OFF_WD1 : OFF_WD0);
#pragma unroll
        for (int ks = 0; ks < 4; ++ks) {
            float a[2][4], b[8][2];
            const int kc = ks * 8 + tg;
#pragma unroll
            for (int mf = 0; mf < 2; mf++) {
                const int r0 = wm * 32 + mf * 16 + gr;
                a[mf][0] = ftf(ESm[r0 * ES_STRIDE + kc]);
                a[mf][1] = ftf(ESm[(r0 + 8) * ES_STRIDE + kc]);
                a[mf][2] = ftf(ESm[r0 * ES_STRIDE + kc + 4]);
                a[mf][3] = ftf(ESm[(r0 + 8) * ES_STRIDE + kc + 4]);
            }
#pragma unroll
            for (int nf = 0; nf < 8; nf++) {
                const int c0 = wn * 64 + nf * 8 + gr;
                b[nf][0] = ftf(Wds[kc * WD_STRIDE + c0]);
                b[nf][1] = ftf(Wds[(kc + 4) * WD_STRIDE + c0]);
            }
#pragma unroll
            for (int mf = 0; mf < 2; mf++)
#pragma unroll
                for (int nf = 0; nf < 8; nf++)
                    mma8(acc[mf][nf], a[mf], b[nf]);
        }
        __syncthreads();   // before buffer reuse next-next iteration
    }

    // epilogue: d = relu(acc + bd); partials of d @ Wo per thread
    float p[2][2][2];      // [mf][rowhalf][class]
#pragma unroll
    for (int mf = 0; mf < 2; mf++)
#pragma unroll
        for (int hh = 0; hh < 2; hh++) { p[mf][hh][0] = 0.f; p[mf][hh][1] = 0.f; }

#pragma unroll
    for (int nf = 0; nf < 8; nf++) {
        const int cb = wn * 64 + nf * 8 + 2 * tg;
        const float bd0 = bd[cb], bd1 = bd[cb + 1];
        const float w00 = Wo[2 * cb + 0], w01 = Wo[2 * cb + 1];
        const float w10 = Wo[2 * cb + 2], w11 = Wo[2 * cb + 3];
#pragma unroll
        for (int mf = 0; mf < 2; mf++) {
            float d0 = fmaxf(acc[mf][nf][0] + bd0, 0.f);
            float d1 = fmaxf(acc[mf][nf][1] + bd1, 0.f);
            float d2 = fmaxf(acc[mf][nf][2] + bd0, 0.f);
            float d3 = fmaxf(acc[mf][nf][3] + bd1, 0.f);
            p[mf][0][0] = fmaf(d0, w00, fmaf(d1, w10, p[mf][0][0]));
            p[mf][0][1] = fmaf(d0, w01, fmaf(d1, w11, p[mf][0][1]));
            p[mf][1][0] = fmaf(d2, w00, fmaf(d3, w10, p[mf][1][0]));
            p[mf][1][1] = fmaf(d2, w01, fmaf(d3, w11, p[mf][1][1]));
        }
    }
    // quad reduce across tg (lanes differing in bits 0,1)
#pragma unroll
    for (int off = 1; off <= 2; off <<= 1)
#pragma unroll
        for (int mf = 0; mf < 2; mf++)
#pragma unroll
            for (int hh = 0; hh < 2; hh++) {
                p[mf][hh][0] += __shfl_xor_sync(0xffffffffu, p[mf][hh][0], off);
                p[mf][hh][1] += __shfl_xor_sync(0xffffffffu, p[mf][hh][1], off);
            }
    float* red = dsm + OFF_RED;    // [wn][row][cls]
    if (tg == 0) {
#pragma unroll
        for (int mf = 0; mf < 2; mf++)
#pragma unroll
            for (int hh = 0; hh < 2; hh++) {
                int r = wm * 32 + mf * 16 + hh * 8 + gr;
                red[(wn * 128 + r) * 2 + 0] = p[mf][hh][0];
                red[(wn * 128 + r) * 2 + 1] = p[mf][hh][1];
            }
    }
    __syncthreads();
    if (tid < 128) {
        float v0 = bo[0], v1 = bo[1];
#pragma unroll
        for (int w = 0; w < 4; w++) {
            v0 += red[(w * 128 + tid) * 2 + 0];
            v1 += red[(w * 128 + tid) * 2 + 1];
        }
        int e = e0 + tid;
        float m = fmaxf(v0, v1);
        float x0 = expf(v0 - m), x1 = expf(v1 - m);
        float inv = 1.0f / (x0 + x1);
        float mk = (float)mask[e];
        out[2 * e + 0] = x0 * inv * mk;
        out[2 * e + 1] = x1 * inv * mk;
    }
}

// ===========================================================================
// gemm_n64 (SIMT): C[M,64] = A[M,K] @ B[K,64], output rounded to tf32.
// ===========================================================================
__global__ __launch_bounds__(256, 2)
void gemm_n64(const float* __restrict__ A, const float* __restrict__ B,
              float* __restrict__ C, int K) {
    const int BM = 128, BK = 32;
    __shared__ float Asm[BK][BM + 4];
    __shared__ float Bsm[BK][64];

    const int tid = threadIdx.x;
    const int tcol = tid & 15;
    const int trow = tid >> 4;
    const int m0 = blockIdx.x * BM;

    float acc[8][4];
#pragma unroll
    for (int r = 0; r < 8; r++)
#pragma unroll
        for (int c = 0; c < 4; c++) acc[r][c] = 0.0f;

    const int lrow = tid >> 3;
    const int lk4 = tid & 7;
    const int brow = tid >> 4;
    const int bc4 = tid & 15;

    const int nchunk = K / BK;
    for (int ch = 0; ch < nchunk; ++ch) {
        const int k0 = ch * BK;
#pragma unroll
        for (int i = 0; i < 4; i++) {
            int r = lrow + 32 * i;
            float4 v = *(const float4*)&A[(size_t)(m0 + r) * K + k0 + lk4 * 4];
            Asm[lk4 * 4 + 0][r] = v.x;
            Asm[lk4 * 4 + 1][r] = v.y;
            Asm[lk4 * 4 + 2][r] = v.z;
            Asm[lk4 * 4 + 3][r] = v.w;
        }
#pragma unroll
        for (int i = 0; i < 2; i++) {
            int r = brow + 16 * i;
            *(float4*)&Bsm[r][bc4 * 4] = *(const float4*)&B[(size_t)(k0 + r) * 64 + bc4 * 4];
        }
        __syncthreads();
#pragma unroll
        for (int k = 0; k < BK; k++) {
            float4 a0 = *(const float4*)&Asm[k][trow * 8];
            float4 a1 = *(const float4*)&Asm[k][trow * 8 + 4];
            float4 b = *(const float4*)&Bsm[k][tcol * 4];
            float ar[8] = {a0.x, a0.y, a0.z, a0.w, a1.x, a1.y, a1.z, a1.w};
            float br[4] = {b.x, b.y, b.z, b.w};
#pragma unroll
            for (int r = 0; r < 8; r++)
#pragma unroll
                for (int c = 0; c < 4; c++) acc[r][c] = fmaf(ar[r], br[c], acc[r][c]);
        }
        __syncthreads();
    }
#pragma unroll
    for (int r = 0; r < 8; r++) {
        float4 o = make_float4(ftf(acc[r][0]), ftf(acc[r][1]), ftf(acc[r][2]), ftf(acc[r][3]));
        *(float4*)&C[(size_t)(m0 + trow * 8 + r) * 64 + tcol * 4] = o;
    }
}

// ===========================================================================
extern "C" void kernel_launch(void* const* d_in, const int* in_sizes, int n_in,
                              void* d_out, int out_size) {
    const float* X     = (const float*)d_in[0];
    const float* Adj   = (const float*)d_in[1];
    const int*   edges = (const int*)d_in[2];
    const int*   smask = (const int*)d_in[3];
    const float* W1    = (const float*)d_in[4];
    const float* b1    = (const float*)d_in[5];
    const float* W2    = (const float*)d_in[6];
    const float* b2    = (const float*)d_in[7];
    const float* Wd    = (const float*)d_in[8];
    const float* bd    = (const float*)d_in[9];
    const float* Wo    = (const float*)d_in[10];
    const float* bo    = (const float*)d_in[11];
    float* out = (float*)d_out;

    float *tmp, *h;
    cudaGetSymbolAddress((void**)&tmp, g_tmp);
    cudaGetSymbolAddress((void**)&h, g_h);

    cudaFuncSetAttribute(adj_mma, cudaFuncAttributeMaxDynamicSharedMemorySize, SMEM_ADJ);
    cudaFuncSetAttribute(edge_mma, cudaFuncAttributeMaxDynamicSharedMemorySize, SMEM_EDGE);

    // layer 1
    gemm_n64<<<NNODES / 128, 256>>>(X, W1, tmp, 128);
    adj_mma<<<NNODES / 128, 256, SMEM_ADJ>>>(Adj, tmp, b1, h);
    // layer 2
    gemm_n64<<<NNODES / 128, 256>>>(h, W2, tmp, 64);
    adj_mma<<<NNODES / 128, 256, SMEM_ADJ>>>(Adj, tmp, b2, h);
    // fused edge MLP (tensor cores)
    edge_mma<<<NEDGES / 128, 512, SMEM_EDGE>>>(h, edges, smask, Wd, bd, Wo, bo, out);
}

// round 6
// speedup vs baseline: 3.4788x; 1.0718x over previous
#include <cuda_runtime.h>
#include <math.h>
#include <stdint.h>

#define NNODES 16384
#define HID 64
#define NEDGES 524288
#define UNITS 256

// scratch buffers
__device__ float g_tmp[NNODES * HID];          // [N,64] B operand (tf32-rounded)
__device__ float g_h[NNODES * HID];            // [N,64]
__device__ float g_part[2 * NNODES * HID];     // split-K partials (8 MB)

// ===========================================================================
// helpers
// ===========================================================================
__device__ __forceinline__ uint32_t smem_u32(const void* p) {
    uint32_t a;
    asm("{ .reg .u64 t; cvta.to.shared.u64 t, %1; cvt.u32.u64 %0, t; }"
        : "=r"(a) : "l"(p));
    return a;
}
__device__ __forceinline__ void cp_async16(uint32_t dst, const void* src) {
    asm volatile("cp.async.cg.shared.global [%0], [%1], 16;" :: "r"(dst), "l"(src));
}
__device__ __forceinline__ void cp_commit() {
    asm volatile("cp.async.commit_group;" ::: "memory");
}
__device__ __forceinline__ float ftf(float x) {   // round fp32 -> tf32 (rna)
    uint32_t u;
    asm("cvt.rna.tf32.f32 %0, %1;" : "=r"(u) : "f"(x));
    return __uint_as_float(u);
}
__device__ __forceinline__ void mma8(float* d, const float* a, const float* b) {
    asm volatile(
        "mma.sync.aligned.m16n8k8.row.col.f32.tf32.tf32.f32 "
        "{%0,%1,%2,%3}, {%4,%5,%6,%7}, {%8,%9}, {%0,%1,%2,%3};"
        : "+f"(d[0]), "+f"(d[1]), "+f"(d[2]), "+f"(d[3])
        : "r"(__float_as_uint(a[0])), "r"(__float_as_uint(a[1])),
          "r"(__float_as_uint(a[2])), "r"(__float_as_uint(a[3])),
          "r"(__float_as_uint(b[0])), "r"(__float_as_uint(b[1])));
}

// ===========================================================================
// adj_mma_sk: split-K partial GEMM. part[y][M,64] = A[M, y-half] @ B[y-half,64]
// BM=128, BN=64, BK=32. 8 warps (4x2), warp tile 32x32. 3-stage cp.async.
// 83 KB smem/CTA -> 2 CTAs/SM (16 warps). Grid (128, 2) fully resident.
// ===========================================================================
#define KSPLIT 2
#define KHALF (NNODES / KSPLIT)     // 8192
#define NITK (KHALF / 32)           // 256
#define A_STRIDE 36
#define B_STRIDE 72
#define STAGE_FLOATS (128 * A_STRIDE + 32 * B_STRIDE)   // 6912
#define SMEM_ADJ (3 * STAGE_FLOATS * 4)                 // 82944 B

__global__ __launch_bounds__(256, 2)
void adj_mma_sk(const float* __restrict__ A, const float* __restrict__ B,
                float* __restrict__ part) {
    extern __shared__ float dsm[];
    const int tid = threadIdx.x;
    const int lane = tid & 31, wid = tid >> 5;
    const int wm = wid >> 1, wn = wid & 1;      // 4x2 warp grid
    const int gr = lane >> 2, tg = lane & 3;
    const int m0 = blockIdx.x * 128;
    const int kbase = blockIdx.y * KHALF;
    float* P = part + (size_t)blockIdx.y * NNODES * HID;

    float acc[2][4][4];
#pragma unroll
    for (int mf = 0; mf < 2; mf++)
#pragma unroll
        for (int nf = 0; nf < 4; nf++)
#pragma unroll
            for (int q = 0; q < 4; q++) acc[mf][nf][q] = 0.0f;

    auto load_tile = [&](int stage, int kt) {
        float* As = dsm + stage * STAGE_FLOATS;
        float* Bs = As + 128 * A_STRIDE;
        const int k0 = kbase + kt * 32;
#pragma unroll
        for (int i = 0; i < 4; i++) {           // A: 128x32 = 1024 granules
            int g = tid + i * 256;
            int r = g >> 3, c = g & 7;
            cp_async16(smem_u32(As + r * A_STRIDE + c * 4),
                       A + (size_t)(m0 + r) * NNODES + k0 + c * 4);
        }
#pragma unroll
        for (int i = 0; i < 2; i++) {           // B: 32x64 = 512 granules
            int g = tid + i * 256;
            int r = g >> 4, c = g & 15;
            cp_async16(smem_u32(Bs + r * B_STRIDE + c * 4),
                       B + (size_t)(k0 + r) * 64 + c * 4);
        }
        cp_commit();
    };

    load_tile(0, 0);
    load_tile(1, 1);

    for (int it = 0; it < NITK; ++it) {
        const int s = it % 3;
        asm volatile("cp.async.wait_group 1;" ::: "memory");
        __syncthreads();
        if (it + 2 < NITK) load_tile((it + 2) % 3, it + 2);
        else cp_commit();

        const float* As = dsm + s * STAGE_FLOATS;
        const float* Bs = As + 128 * A_STRIDE;

#pragma unroll
        for (int ks = 0; ks < 4; ++ks) {
            float a[2][4], b[4][2];
            const int kc = ks * 8 + tg;
#pragma unroll
            for (int mf = 0; mf < 2; mf++) {
                const int r0 = wm * 32 + mf * 16 + gr;
                a[mf][0] = As[r0 * A_STRIDE + kc];          // HW truncates to tf32
                a[mf][1] = As[(r0 + 8) * A_STRIDE + kc];
                a[mf][2] = As[r0 * A_STRIDE + kc + 4];
                a[mf][3] = As[(r0 + 8) * A_STRIDE + kc + 4];
            }
#pragma unroll
            for (int nf = 0; nf < 4; nf++) {
                const int c0 = wn * 32 + nf * 8 + gr;
                b[nf][0] = Bs[kc * B_STRIDE + c0];          // B pre-rounded to tf32
                b[nf][1] = Bs[(kc + 4) * B_STRIDE + c0];
            }
#pragma unroll
            for (int mf = 0; mf < 2; mf++)
#pragma unroll
                for (int nf = 0; nf < 4; nf++)
                    mma8(acc[mf][nf], a[mf], b[nf]);
        }
    }

    // epilogue: raw partials
#pragma unroll
    for (int mf = 0; mf < 2; mf++) {
#pragma unroll
        for (int nf = 0; nf < 4; nf++) {
            const int row = m0 + wm * 32 + mf * 16 + gr;
            const int col = wn * 32 + nf * 8 + 2 * tg;
            *(float2*)&P[(size_t)row * 64 + col] =
                make_float2(acc[mf][nf][0], acc[mf][nf][1]);
            *(float2*)&P[(size_t)(row + 8) * 64 + col] =
                make_float2(acc[mf][nf][2], acc[mf][nf][3]);
        }
    }
}

// ===========================================================================
// reduce_sigmoid: C = sigmoid(part0 + part1 + bias)   [N*64 elems]
// ===========================================================================
__global__ __launch_bounds__(256)
void reduce_sigmoid(const float* __restrict__ part, const float* __restrict__ bias,
                    float* __restrict__ C) {
    const int i = blockIdx.x * 256 + threadIdx.x;           // float4 index
    const float4 p0 = *(const float4*)&part[i * 4];
    const float4 p1 = *(const float4*)&part[NNODES * HID + i * 4];
    const float4 bb = *(const float4*)&bias[(i * 4) & 63];
    float4 o;
    o.x = 1.0f / (1.0f + expf(-(p0.x + p1.x + bb.x)));
    o.y = 1.0f / (1.0f + expf(-(p0.y + p1.y + bb.y)));
    o.z = 1.0f / (1.0f + expf(-(p0.z + p1.z + bb.z)));
    o.w = 1.0f / (1.0f + expf(-(p0.w + p1.w + bb.w)));
    *(float4*)&C[i * 4] = o;
}

// ===========================================================================
// edge_mma: fused  relu(concat(h[src],h[dst]) @ Wd + bd) @ Wo -> softmax*mask
// BM=128 edges, BN=256 units, K=128 in 4 chunks of 32. 512 threads (4x4).
// ===========================================================================
#define ES_STRIDE 36
#define WD_STRIDE 264
#define ES_FLOATS (128 * ES_STRIDE)
#define WD_FLOATS (32 * WD_STRIDE)
#define OFF_ES0 0
#define OFF_ES1 ES_FLOATS
#define OFF_WD0 (2 * ES_FLOATS)
#define OFF_WD1 (2 * ES_FLOATS + WD_FLOATS)
#define OFF_RED (2 * ES_FLOATS + 2 * WD_FLOATS)
#define SMEM_EDGE ((OFF_RED + 4 * 128 * 2) * 4)

__global__ __launch_bounds__(512, 1)
void edge_mma(const float* __restrict__ h, const int* __restrict__ edges,
              const int* __restrict__ mask,
              const float* __restrict__ Wd, const float* __restrict__ bd,
              const float* __restrict__ Wo, const float* __restrict__ bo,
              float* __restrict__ out) {
    extern __shared__ float dsm[];
    const int tid = threadIdx.x;
    const int lane = tid & 31, wid = tid >> 5;
    const int wm = wid >> 2, wn = wid & 3;
    const int gr = lane >> 2, tg = lane & 3;
    const int e0 = blockIdx.x * 128;

    float acc[2][8][4];
#pragma unroll
    for (int mf = 0; mf < 2; mf++)
#pragma unroll
        for (int nf = 0; nf < 8; nf++)
#pragma unroll
            for (int q = 0; q < 4; q++) acc[mf][nf][q] = 0.0f;

    auto load_chunk = [&](int ch, int buf) {
        float* ESm = dsm + (buf ? OFF_ES1 : OFF_ES0);
        float* Wds = dsm + (buf ? OFF_WD1 : OFF_WD0);
        const int sel = ch >> 1, hcol0 = (ch & 1) * 32;
#pragma unroll
        for (int i = 0; i < 2; i++) {
            int g = tid + i * 512;
            int e = g >> 3, c = g & 7;
            int node = __ldg(&edges[2 * (e0 + e) + sel]);
            cp_async16(smem_u32(ESm + e * ES_STRIDE + c * 4),
                       h + (size_t)node * 64 + hcol0 + c * 4);
        }
#pragma unroll
        for (int i = 0; i < 4; i++) {
            int g = tid + i * 512;
            int r = g >> 6, c = g & 63;
            cp_async16(smem_u32(Wds + r * WD_STRIDE + c * 4),
                       Wd + (size_t)(ch * 32 + r) * UNITS + c * 4);
        }
        cp_commit();
    };

    load_chunk(0, 0);
    for (int ch = 0; ch < 4; ++ch) {
        if (ch + 1 < 4) load_chunk(ch + 1, (ch + 1) & 1);
        else cp_commit();
        asm volatile("cp.async.wait_group 1;" ::: "memory");
        __syncthreads();

        const float* ESm = dsm + ((ch & 1) ? OFF_ES1 : OFF_ES0);
        const float* Wds = dsm + ((ch & 1) ? OFF_WD1 : OFF_WD0);
#pragma unroll
        for (int ks = 0; ks < 4; ++ks) {
            float a[2][4], b[8][2];
            const int kc = ks * 8 + tg;
#pragma unroll
            for (int mf = 0; mf < 2; mf++) {
                const int r0 = wm * 32 + mf * 16 + gr;
                a[mf][0] = ESm[r0 * ES_STRIDE + kc];
                a[mf][1] = ESm[(r0 + 8) * ES_STRIDE + kc];
                a[mf][2] = ESm[r0 * ES_STRIDE + kc + 4];
                a[mf][3] = ESm[(r0 + 8) * ES_STRIDE + kc + 4];
            }
#pragma unroll
            for (int nf = 0; nf < 8; nf++) {
                const int c0 = wn * 64 + nf * 8 + gr;
                b[nf][0] = Wds[kc * WD_STRIDE + c0];
                b[nf][1] = Wds[(kc + 4) * WD_STRIDE + c0];
            }
#pragma unroll
            for (int mf = 0; mf < 2; mf++)
#pragma unroll
                for (int nf = 0; nf < 8; nf++)
                    mma8(acc[mf][nf], a[mf], b[nf]);
        }
        __syncthreads();
    }

    // epilogue: relu + Wo contraction in registers
    float p[2][2][2];
#pragma unroll
    for (int mf = 0; mf < 2; mf++)
#pragma unroll
        for (int hh = 0; hh < 2; hh++) { p[mf][hh][0] = 0.f; p[mf][hh][1] = 0.f; }

#pragma unroll
    for (int nf = 0; nf < 8; nf++) {
        const int cb = wn * 64 + nf * 8 + 2 * tg;
        const float bd0 = bd[cb], bd1 = bd[cb + 1];
        const float w00 = Wo[2 * cb + 0], w01 = Wo[2 * cb + 1];
        const float w10 = Wo[2 * cb + 2], w11 = Wo[2 * cb + 3];
#pragma unroll
        for (int mf = 0; mf < 2; mf++) {
            float d0 = fmaxf(acc[mf][nf][0] + bd0, 0.f);
            float d1 = fmaxf(acc[mf][nf][1] + bd1, 0.f);
            float d2 = fmaxf(acc[mf][nf][2] + bd0, 0.f);
            float d3 = fmaxf(acc[mf][nf][3] + bd1, 0.f);
            p[mf][0][0] = fmaf(d0, w00, fmaf(d1, w10, p[mf][0][0]));
            p[mf][0][1] = fmaf(d0, w01, fmaf(d1, w11, p[mf][0][1]));
            p[mf][1][0] = fmaf(d2, w00, fmaf(d3, w10, p[mf][1][0]));
            p[mf][1][1] = fmaf(d2, w01, fmaf(d3, w11, p[mf][1][1]));
        }
    }
#pragma unroll
    for (int off = 1; off <= 2; off <<= 1)
#pragma unroll
        for (int mf = 0; mf < 2; mf++)
#pragma unroll
            for (int hh = 0; hh < 2; hh++) {
                p[mf][hh][0] += __shfl_xor_sync(0xffffffffu, p[mf][hh][0], off);
                p[mf][hh][1] += __shfl_xor_sync(0xffffffffu, p[mf][hh][1], off);
            }
    float* red = dsm + OFF_RED;
    if (tg == 0) {
#pragma unroll
        for (int mf = 0; mf < 2; mf++)
#pragma unroll
            for (int hh = 0; hh < 2; hh++) {
                int r = wm * 32 + mf * 16 + hh * 8 + gr;
                red[(wn * 128 + r) * 2 + 0] = p[mf][hh][0];
                red[(wn * 128 + r) * 2 + 1] = p[mf][hh][1];
            }
    }
    __syncthreads();
    if (tid < 128) {
        float v0 = bo[0], v1 = bo[1];
#pragma unroll
        for (int w = 0; w < 4; w++) {
            v0 += red[(w * 128 + tid) * 2 + 0];
            v1 += red[(w * 128 + tid) * 2 + 1];
        }
        int e = e0 + tid;
        float m = fmaxf(v0, v1);
        float x0 = expf(v0 - m), x1 = expf(v1 - m);
        float inv = 1.0f / (x0 + x1);
        float mk = (float)mask[e];
        out[2 * e + 0] = x0 * inv * mk;
        out[2 * e + 1] = x1 * inv * mk;
    }
}

// ===========================================================================
// gemm_n64 (SIMT): C[M,64] = A[M,K] @ B[K,64], output rounded to tf32.
// ===========================================================================
__global__ __launch_bounds__(256, 2)
void gemm_n64(const float* __restrict__ A, const float* __restrict__ B,
              float* __restrict__ C, int K) {
    const int BM = 128, BK = 32;
    __shared__ float Asm[BK][BM + 4];
    __shared__ float Bsm[BK][64];

    const int tid = threadIdx.x;
    const int tcol = tid & 15;
    const int trow = tid >> 4;
    const int m0 = blockIdx.x * BM;

    float acc[8][4];
#pragma unroll
    for (int r = 0; r < 8; r++)
#pragma unroll
        for (int c = 0; c < 4; c++) acc[r][c] = 0.0f;

    const int lrow = tid >> 3;
    const int lk4 = tid & 7;
    const int brow = tid >> 4;
    const int bc4 = tid & 15;

    const int nchunk = K / BK;
    for (int ch = 0; ch < nchunk; ++ch) {
        const int k0 = ch * BK;
#pragma unroll
        for (int i = 0; i < 4; i++) {
            int r = lrow + 32 * i;
            float4 v = *(const float4*)&A[(size_t)(m0 + r) * K + k0 + lk4 * 4];
            Asm[lk4 * 4 + 0][r] = v.x;
            Asm[lk4 * 4 + 1][r] = v.y;
            Asm[lk4 * 4 + 2][r] = v.z;
            Asm[lk4 * 4 + 3][r] = v.w;
        }
#pragma unroll
        for (int i = 0; i < 2; i++) {
            int r = brow + 16 * i;
            *(float4*)&Bsm[r][bc4 * 4] = *(const float4*)&B[(size_t)(k0 + r) * 64 + bc4 * 4];
        }
        __syncthreads();
#pragma unroll
        for (int k = 0; k < BK; k++) {
            float4 a0 = *(const float4*)&Asm[k][trow * 8];
            float4 a1 = *(const float4*)&Asm[k][trow * 8 + 4];
            float4 b = *(const float4*)&Bsm[k][tcol * 4];
            float ar[8] = {a0.x, a0.y, a0.z, a0.w, a1.x, a1.y, a1.z, a1.w};
            float br[4] = {b.x, b.y, b.z, b.w};
#pragma unroll
            for (int r = 0; r < 8; r++)
#pragma unroll
                for (int c = 0; c < 4; c++) acc[r][c] = fmaf(ar[r], br[c], acc[r][c]);
        }
        __syncthreads();
    }
#pragma unroll
    for (int r = 0; r < 8; r++) {
        float4 o = make_float4(ftf(acc[r][0]), ftf(acc[r][1]), ftf(acc[r][2]), ftf(acc[r][3]));
        *(float4*)&C[(size_t)(m0 + trow * 8 + r) * 64 + tcol * 4] = o;
    }
}

// ===========================================================================
extern "C" void kernel_launch(void* const* d_in, const int* in_sizes, int n_in,
                              void* d_out, int out_size) {
    const float* X     = (const float*)d_in[0];
    const float* Adj   = (const float*)d_in[1];
    const int*   edges = (const int*)d_in[2];
    const int*   smask = (const int*)d_in[3];
    const float* W1    = (const float*)d_in[4];
    const float* b1    = (const float*)d_in[5];
    const float* W2    = (const float*)d_in[6];
    const float* b2    = (const float*)d_in[7];
    const float* Wd    = (const float*)d_in[8];
    const float* bd    = (const float*)d_in[9];
    const float* Wo    = (const float*)d_in[10];
    const float* bo    = (const float*)d_in[11];
    float* out = (float*)d_out;

    float *tmp, *h, *part;
    cudaGetSymbolAddress((void**)&tmp, g_tmp);
    cudaGetSymbolAddress((void**)&h, g_h);
    cudaGetSymbolAddress((void**)&part, g_part);

    cudaFuncSetAttribute(adj_mma_sk, cudaFuncAttributeMaxDynamicSharedMemorySize, SMEM_ADJ);
    cudaFuncSetAttribute(edge_mma, cudaFuncAttributeMaxDynamicSharedMemorySize, SMEM_EDGE);

    dim3 agrid(NNODES / 128, KSPLIT);
    const int rgrid = (NNODES * HID / 4) / 256;

    // layer 1
    gemm_n64<<<NNODES / 128, 256>>>(X, W1, tmp, 128);
    adj_mma_sk<<<agrid, 256, SMEM_ADJ>>>(Adj, tmp, part);
    reduce_sigmoid<<<rgrid, 256>>>(part, b1, h);
    // layer 2
    gemm_n64<<<NNODES / 128, 256>>>(h, W2, tmp, 64);
    adj_mma_sk<<<agrid, 256, SMEM_ADJ>>>(Adj, tmp, part);
    reduce_sigmoid<<<rgrid, 256>>>(part, b2, h);
    // fused edge MLP
    edge_mma<<<NEDGES / 128, 512, SMEM_EDGE>>>(h, edges, smask, Wd, bd, Wo, bo, out);
}

// round 7
// speedup vs baseline: 4.5915x; 1.3199x over previous
#include <cuda_runtime.h>
#include <cuda_fp16.h>
#include <math.h>
#include <stdint.h>

#define NNODES 16384
#define HID 64
#define NEDGES 524288
#define UNITS 256
#define ASCALE 16384.0f
#define ASCALE_INV 6.103515625e-05f

// scratch
__device__ __half g_ah[(size_t)NNODES * NNODES];   // A as fp16*16384 (512 MB)
__device__ float  g_tmp[NNODES * HID];             // XW fp32 [N][64]
__device__ __half g_bt[HID * NNODES];              // XW fp16 transposed [64][N]
__device__ float  g_h[NNODES * HID];               // layer-1 h fp32
__device__ __half g_h16[NNODES * HID];             // layer-2 h fp16
__device__ float  g_part[2 * NNODES * HID];        // split-K partials
__device__ __half g_wdt[UNITS * 2 * HID];          // Wd^T fp16 [256][128]

// ===========================================================================
// helpers
// ===========================================================================
__device__ __forceinline__ uint32_t smem_u32(const void* p) {
    uint32_t a;
    asm("{ .reg .u64 t; cvta.to.shared.u64 t, %1; cvt.u32.u64 %0, t; }"
        : "=r"(a) : "l"(p));
    return a;
}
__device__ __forceinline__ void cp_async16(uint32_t dst, const void* src) {
    asm volatile("cp.async.cg.shared.global [%0], [%1], 16;" :: "r"(dst), "l"(src));
}
__device__ __forceinline__ void cp_commit() {
    asm volatile("cp.async.commit_group;" ::: "memory");
}
__device__ __forceinline__ void ldsm_x4(uint32_t* r, uint32_t addr) {
    asm volatile("ldmatrix.sync.aligned.m8n8.x4.shared.b16 {%0,%1,%2,%3}, [%4];"
                 : "=r"(r[0]), "=r"(r[1]), "=r"(r[2]), "=r"(r[3]) : "r"(addr));
}
__device__ __forceinline__ void mma16(float* d, const uint32_t* a, uint32_t b0, uint32_t b1) {
    asm volatile(
        "mma.sync.aligned.m16n8k16.row.col.f32.f16.f16.f32 "
        "{%0,%1,%2,%3}, {%4,%5,%6,%7}, {%8,%9}, {%0,%1,%2,%3};"
        : "+f"(d[0]), "+f"(d[1]), "+f"(d[2]), "+f"(d[3])
        : "r"(a[0]), "r"(a[1]), "r"(a[2]), "r"(a[3]), "r"(b0), "r"(b1));
}

// ===========================================================================
// convert_a: Ah = fp16(A * 16384)   (1 GiB read, 0.5 GiB write, streaming)
// ===========================================================================
__global__ __launch_bounds__(256)
void convert_a(const float* __restrict__ A, __half* __restrict__ Ah) {
    const size_t nunits = (size_t)NNODES * NNODES / 8;
    const size_t stride = (size_t)gridDim.x * 256;
    for (size_t u = (size_t)blockIdx.x * 256 + threadIdx.x; u < nunits; u += stride) {
        float4 v0 = *(const float4*)(A + u * 8);
        float4 v1 = *(const float4*)(A + u * 8 + 4);
        __half2 h0 = __floats2half2_rn(v0.x * ASCALE, v0.y * ASCALE);
        __half2 h1 = __floats2half2_rn(v0.z * ASCALE, v0.w * ASCALE);
        __half2 h2 = __floats2half2_rn(v1.x * ASCALE, v1.y * ASCALE);
        __half2 h3 = __floats2half2_rn(v1.z * ASCALE, v1.w * ASCALE);
        uint4 o;
        o.x = *reinterpret_cast<uint32_t*>(&h0);
        o.y = *reinterpret_cast<uint32_t*>(&h1);
        o.z = *reinterpret_cast<uint32_t*>(&h2);
        o.w = *reinterpret_cast<uint32_t*>(&h3);
        *(uint4*)(Ah + u * 8) = o;
    }
}

// ===========================================================================
// transpose + fp32->fp16: in [RIN][CIN] f32 -> out [CIN][RIN] half
// ===========================================================================
template <int RIN, int CIN>
__global__ void transpose_h(const float* __restrict__ in, __half* __restrict__ out) {
    __shared__ float t[32][33];
    const int bx = blockIdx.x, by = blockIdx.y;
    const int x = threadIdx.x, y = threadIdx.y;   // 32 x 8
#pragma unroll
    for (int i = 0; i < 32; i += 8)
        t[y + i][x] = in[(size_t)(bx * 32 + y + i) * CIN + by * 32 + x];
    __syncthreads();
#pragma unroll
    for (int i = 0; i < 32; i += 8)
        out[(size_t)(by * 32 + y + i) * RIN + bx * 32 + x] = __float2half(t[x][y + i]);
}

// ===========================================================================
// adj_mma_h: part[y][M,64] = Ah[M, y-half] @ Bt[64, y-half]^T  (fp16 m16n8k16)
// BM=128, BN=64, BK=64. 8 warps (4x2), warp tile 32x32, LDSM fragments.
// 81 KB smem -> 2 CTAs/SM. Grid (128, 2).
// ===========================================================================
#define KSPLIT 2
#define KHALF (NNODES / KSPLIT)
#define NIT (KHALF / 64)            // 128
#define ADJ_AST 144                 // A row bytes: 64 fp16 = 128 + 16 pad
#define ADJ_BST 144
#define ADJ_STAGE (128 * ADJ_AST + 64 * ADJ_BST)   // 27648
#define SMEM_ADJ (3 * ADJ_STAGE)                   // 82944

__global__ __launch_bounds__(256, 2)
void adj_mma_h(const __half* __restrict__ A, const __half* __restrict__ Bt,
               float* __restrict__ part) {
    extern __shared__ char dsm[];
    const uint32_t sbase = smem_u32(dsm);
    const int tid = threadIdx.x;
    const int lane = tid & 31, wid = tid >> 5;
    const int wm = wid >> 1, wn = wid & 1;
    const int gr = lane >> 2, tg = lane & 3;
    const int m0 = blockIdx.x * 128;
    const int kbase = blockIdx.y * KHALF;
    float* P = part + (size_t)blockIdx.y * NNODES * HID;

    // per-lane ldmatrix offsets
    const uint32_t aoff = (uint32_t)(((lane & 7) + ((lane >> 3) & 1) * 8) * ADJ_AST
                                     + ((lane >> 4) & 1) * 16);
    const uint32_t boff = (uint32_t)(((lane & 7) + ((lane >> 4) & 1) * 8) * ADJ_BST
                                     + ((lane >> 3) & 1) * 16);

    float acc[2][4][4];
#pragma unroll
    for (int mf = 0; mf < 2; mf++)
#pragma unroll
        for (int nf = 0; nf < 4; nf++)
#pragma unroll
            for (int q = 0; q < 4; q++) acc[mf][nf][q] = 0.0f;

    auto load_tile = [&](int stage, int kt) {
        uint32_t sa = sbase + stage * ADJ_STAGE;
        uint32_t sb = sa + 128 * ADJ_AST;
        const int k0 = kbase + kt * 64;
#pragma unroll
        for (int i = 0; i < 4; i++) {     // A: 128 rows x 8 granules
            int g = tid + i * 256;
            int r = g >> 3, c = g & 7;
            cp_async16(sa + r * ADJ_AST + c * 16,
                       A + (size_t)(m0 + r) * NNODES + k0 + c * 8);
        }
#pragma unroll
        for (int i = 0; i < 2; i++) {     // B: 64 rows x 8 granules
            int g = tid + i * 256;
            int r = g >> 3, c = g & 7;
            cp_async16(sb + r * ADJ_BST + c * 16,
                       Bt + (size_t)r * NNODES + k0 + c * 8);
        }
        cp_commit();
    };

    load_tile(0, 0);
    load_tile(1, 1);

    for (int it = 0; it < NIT; ++it) {
        const int s = it % 3;
        asm volatile("cp.async.wait_group 1;" ::: "memory");
        __syncthreads();
        if (it + 2 < NIT) load_tile((it + 2) % 3, it + 2);
        else cp_commit();

        const uint32_t sa = sbase + s * ADJ_STAGE;
        const uint32_t sb = sa + 128 * ADJ_AST;

#pragma unroll
        for (int ks = 0; ks < 4; ++ks) {
            uint32_t a[2][4], bq[2][4];
#pragma unroll
            for (int mf = 0; mf < 2; mf++)
                ldsm_x4(a[mf], sa + (wm * 32 + mf * 16) * ADJ_AST + ks * 32 + aoff);
#pragma unroll
            for (int p = 0; p < 2; p++)
                ldsm_x4(bq[p], sb + (wn * 32 + p * 16) * ADJ_BST + ks * 32 + boff);
#pragma unroll
            for (int mf = 0; mf < 2; mf++)
#pragma unroll
                for (int p = 0; p < 2; p++) {
                    mma16(acc[mf][2 * p + 0], a[mf], bq[p][0], bq[p][1]);
                    mma16(acc[mf][2 * p + 1], a[mf], bq[p][2], bq[p][3]);
                }
        }
    }

    // epilogue: raw (scaled) partials
#pragma unroll
    for (int mf = 0; mf < 2; mf++) {
#pragma unroll
        for (int nf = 0; nf < 4; nf++) {
            const int row = m0 + wm * 32 + mf * 16 + gr;
            const int col = wn * 32 + nf * 8 + 2 * tg;
            *(float2*)&P[(size_t)row * 64 + col] =
                make_float2(acc[mf][nf][0], acc[mf][nf][1]);
            *(float2*)&P[(size_t)(row + 8) * 64 + col] =
                make_float2(acc[mf][nf][2], acc[mf][nf][3]);
        }
    }
}

// ===========================================================================
// reduce: C = sigmoid((p0+p1)*ASCALE_INV + bias); fp32 or fp16 output
// ===========================================================================
__global__ __launch_bounds__(256)
void reduce_sigmoid_f(const float* __restrict__ part, const float* __restrict__ bias,
                      float* __restrict__ C) {
    const int i = blockIdx.x * 256 + threadIdx.x;
    const float4 p0 = *(const float4*)&part[i * 4];
    const float4 p1 = *(const float4*)&part[NNODES * HID + i * 4];
    const float4 bb = *(const float4*)&bias[(i * 4) & 63];
    float4 o;
    o.x = 1.0f / (1.0f + expf(-((p0.x + p1.x) * ASCALE_INV + bb.x)));
    o.y = 1.0f / (1.0f + expf(-((p0.y + p1.y) * ASCALE_INV + bb.y)));
    o.z = 1.0f / (1.0f + expf(-((p0.z + p1.z) * ASCALE_INV + bb.z)));
    o.w = 1.0f / (1.0f + expf(-((p0.w + p1.w) * ASCALE_INV + bb.w)));
    *(float4*)&C[i * 4] = o;
}
__global__ __launch_bounds__(256)
void reduce_sigmoid_h(const float* __restrict__ part, const float* __restrict__ bias,
                      __half* __restrict__ C) {
    const int i = blockIdx.x * 256 + threadIdx.x;
    const float4 p0 = *(const float4*)&part[i * 4];
    const float4 p1 = *(const float4*)&part[NNODES * HID + i * 4];
    const float4 bb = *(const float4*)&bias[(i * 4) & 63];
    float ox = 1.0f / (1.0f + expf(-((p0.x + p1.x) * ASCALE_INV + bb.x)));
    float oy = 1.0f / (1.0f + expf(-((p0.y + p1.y) * ASCALE_INV + bb.y)));
    float oz = 1.0f / (1.0f + expf(-((p0.z + p1.z) * ASCALE_INV + bb.z)));
    float ow = 1.0f / (1.0f + expf(-((p0.w + p1.w) * ASCALE_INV + bb.w)));
    __half2 h0 = __floats2half2_rn(ox, oy);
    __half2 h1 = __floats2half2_rn(oz, ow);
    uint2 st;
    st.x = *reinterpret_cast<uint32_t*>(&h0);
    st.y = *reinterpret_cast<uint32_t*>(&h1);
    *(uint2*)&C[i * 4] = st;
}

// ===========================================================================
// edge_mma_h: fused relu(concat(h[s],h[d]) @ Wd + bd) @ Wo -> softmax * mask
// fp16 m16n8k16. 512 threads (4x4 warps, warp tile 32x64), BM=128, BN=256.
// WdT fp16 [256][128] preloaded whole into smem; ES double-buffered.
// ===========================================================================
#define E_WST 272                        // WdT row bytes (128 fp16 + pad)
#define E_EST 80                         // ES row bytes (32 fp16 + pad)
#define OFF_WD 0
#define OFF_ES0 (256 * E_WST)            // 69632
#define OFF_ES1 (OFF_ES0 + 128 * E_EST)
#define OFF_RED (OFF_ES1 + 128 * E_EST)
#define SMEM_EDGE (OFF_RED + 4096)       // 94208

__global__ __launch_bounds__(512, 1)
void edge_mma_h(const __half* __restrict__ h, const int* __restrict__ edges,
                const int* __restrict__ mask, const __half* __restrict__ WdT,
                const float* __restrict__ bd, const float* __restrict__ Wo,
                const float* __restrict__ bo, float* __restrict__ out) {
    extern __shared__ char dsm[];
    const uint32_t sbase = smem_u32(dsm);
    const int tid = threadIdx.x;
    const int lane = tid & 31, wid = tid >> 5;
    const int wm = wid >> 2, wn = wid & 3;
    const int gr = lane >> 2, tg = lane & 3;
    const int e0 = blockIdx.x * 128;

    const uint32_t aoff = (uint32_t)(((lane & 7) + ((lane >> 3) & 1) * 8) * E_EST
                                     + ((lane >> 4) & 1) * 16);
    const uint32_t boff = (uint32_t)(((lane & 7) + ((lane >> 4) & 1) * 8) * E_WST
                                     + ((lane >> 3) & 1) * 16);

    float acc[2][8][4];
#pragma unroll
    for (int mf = 0; mf < 2; mf++)
#pragma unroll
        for (int nf = 0; nf < 8; nf++)
#pragma unroll
            for (int q = 0; q < 4; q++) acc[mf][nf][q] = 0.0f;

    // preload full WdT (4096 granules)
#pragma unroll
    for (int i = 0; i < 8; i++) {
        int g = tid + i * 512;
        int r = g >> 4, c = g & 15;
        cp_async16(sbase + OFF_WD + r * E_WST + c * 16, WdT + (size_t)r * 128 + c * 8);
    }
    cp_commit();

    auto load_es = [&](int ch) {
        uint32_t es = sbase + ((ch & 1) ? OFF_ES1 : OFF_ES0);
        const int sel = ch >> 1, hc = (ch & 1) * 32;
        int e = tid >> 2, c = tid & 3;
        int node = __ldg(&edges[2 * (e0 + e) + sel]);
        cp_async16(es + e * E_EST + c * 16, h + (size_t)node * 64 + hc + c * 8);
        cp_commit();
    };

    load_es(0);
    for (int ch = 0; ch < 4; ++ch) {
        if (ch < 3) load_es(ch + 1);
        else cp_commit();
        asm volatile("cp.async.wait_group 1;" ::: "memory");
        __syncthreads();

        const uint32_t es = sbase + ((ch & 1) ? OFF_ES1 : OFF_ES0);
        const uint32_t wd = sbase + OFF_WD;
#pragma unroll
        for (int ks2 = 0; ks2 < 2; ++ks2) {
            uint32_t a[2][4], bq[4][4];
            const int kglob = ch * 2 + ks2;
#pragma unroll
            for (int mf = 0; mf < 2; mf++)
                ldsm_x4(a[mf], es + (wm * 32 + mf * 16) * E_EST + ks2 * 32 + aoff);
#pragma unroll
            for (int p = 0; p < 4; p++)
                ldsm_x4(bq[p], wd + (wn * 64 + p * 16) * E_WST + kglob * 32 + boff);
#pragma unroll
            for (int mf = 0; mf < 2; mf++)
#pragma unroll
                for (int p = 0; p < 4; p++) {
                    mma16(acc[mf][2 * p + 0], a[mf], bq[p][0], bq[p][1]);
                    mma16(acc[mf][2 * p + 1], a[mf], bq[p][2], bq[p][3]);
                }
        }
        __syncthreads();
    }

    // epilogue: relu + Wo contraction in registers
    float p[2][2][2];
#pragma unroll
    for (int mf = 0; mf < 2; mf++)
#pragma unroll
        for (int hh = 0; hh < 2; hh++) { p[mf][hh][0] = 0.f; p[mf][hh][1] = 0.f; }

#pragma unroll
    for (int nf = 0; nf < 8; nf++) {
        const int cb = wn * 64 + nf * 8 + 2 * tg;
        const float bd0 = bd[cb], bd1 = bd[cb + 1];
        const float w00 = Wo[2 * cb + 0], w01 = Wo[2 * cb + 1];
        const float w10 = Wo[2 * cb + 2], w11 = Wo[2 * cb + 3];
#pragma unroll
        for (int mf = 0; mf < 2; mf++) {
            float d0 = fmaxf(acc[mf][nf][0] + bd0, 0.f);
            float d1 = fmaxf(acc[mf][nf][1] + bd1, 0.f);
            float d2 = fmaxf(acc[mf][nf][2] + bd0, 0.f);
            float d3 = fmaxf(acc[mf][nf][3] + bd1, 0.f);
            p[mf][0][0] = fmaf(d0, w00, fmaf(d1, w10, p[mf][0][0]));
            p[mf][0][1] = fmaf(d0, w01, fmaf(d1, w11, p[mf][0][1]));
            p[mf][1][0] = fmaf(d2, w00, fmaf(d3, w10, p[mf][1][0]));
            p[mf][1][1] = fmaf(d2, w01, fmaf(d3, w11, p[mf][1][1]));
        }
    }
#pragma unroll
    for (int off = 1; off <= 2; off <<= 1)
#pragma unroll
        for (int mf = 0; mf < 2; mf++)
#pragma unroll
            for (int hh = 0; hh < 2; hh++) {
                p[mf][hh][0] += __shfl_xor_sync(0xffffffffu, p[mf][hh][0], off);
                p[mf][hh][1] += __shfl_xor_sync(0xffffffffu, p[mf][hh][1], off);
            }
    float* red = (float*)(dsm + OFF_RED);
    if (tg == 0) {
#pragma unroll
        for (int mf = 0; mf < 2; mf++)
#pragma unroll
            for (int hh = 0; hh < 2; hh++) {
                int r = wm * 32 + mf * 16 + hh * 8 + gr;
                red[(wn * 128 + r) * 2 + 0] = p[mf][hh][0];
                red[(wn * 128 + r) * 2 + 1] = p[mf][hh][1];
            }
    }
    __syncthreads();
    if (tid < 128) {
        float v0 = bo[0], v1 = bo[1];
#pragma unroll
        for (int w = 0; w < 4; w++) {
            v0 += red[(w * 128 + tid) * 2 + 0];
            v1 += red[(w * 128 + tid) * 2 + 1];
        }
        int e = e0 + tid;
        float m = fmaxf(v0, v1);
        float x0 = expf(v0 - m), x1 = expf(v1 - m);
        float inv = 1.0f / (x0 + x1);
        float mk = (float)mask[e];
        out[2 * e + 0] = x0 * inv * mk;
        out[2 * e + 1] = x1 * inv * mk;
    }
}

// ===========================================================================
// gemm_n64 (SIMT): C[M,64] = A[M,K] @ B[K,64]  (small K: 128/64)
// ===========================================================================
__global__ __launch_bounds__(256, 2)
void gemm_n64(const float* __restrict__ A, const float* __restrict__ B,
              float* __restrict__ C, int K) {
    const int BM = 128, BK = 32;
    __shared__ float Asm[BK][BM + 4];
    __shared__ float Bsm[BK][64];

    const int tid = threadIdx.x;
    const int tcol = tid & 15;
    const int trow = tid >> 4;
    const int m0 = blockIdx.x * BM;

    float acc[8][4];
#pragma unroll
    for (int r = 0; r < 8; r++)
#pragma unroll
        for (int c = 0; c < 4; c++) acc[r][c] = 0.0f;

    const int lrow = tid >> 3;
    const int lk4 = tid & 7;
    const int brow = tid >> 4;
    const int bc4 = tid & 15;

    const int nchunk = K / BK;
    for (int ch = 0; ch < nchunk; ++ch) {
        const int k0 = ch * BK;
#pragma unroll
        for (int i = 0; i < 4; i++) {
            int r = lrow + 32 * i;
            float4 v = *(const float4*)&A[(size_t)(m0 + r) * K + k0 + lk4 * 4];
            Asm[lk4 * 4 + 0][r] = v.x;
            Asm[lk4 * 4 + 1][r] = v.y;
            Asm[lk4 * 4 + 2][r] = v.z;
            Asm[lk4 * 4 + 3][r] = v.w;
        }
#pragma unroll
        for (int i = 0; i < 2; i++) {
            int r = brow + 16 * i;
            *(float4*)&Bsm[r][bc4 * 4] = *(const float4*)&B[(size_t)(k0 + r) * 64 + bc4 * 4];
        }
        __syncthreads();
#pragma unroll
        for (int k = 0; k < BK; k++) {
            float4 a0 = *(const float4*)&Asm[k][trow * 8];
            float4 a1 = *(const float4*)&Asm[k][trow * 8 + 4];
            float4 b = *(const float4*)&Bsm[k][tcol * 4];
            float ar[8] = {a0.x, a0.y, a0.z, a0.w, a1.x, a1.y, a1.z, a1.w};
            float br[4] = {b.x, b.y, b.z, b.w};
#pragma unroll
            for (int r = 0; r < 8; r++)
#pragma unroll
                for (int c = 0; c < 4; c++) acc[r][c] = fmaf(ar[r], br[c], acc[r][c]);
        }
        __syncthreads();
    }
#pragma unroll
    for (int r = 0; r < 8; r++) {
        float4 o = make_float4(acc[r][0], acc[r][1], acc[r][2], acc[r][3]);
        *(float4*)&C[(size_t)(m0 + trow * 8 + r) * 64 + tcol * 4] = o;
    }
}

// ===========================================================================
extern "C" void kernel_launch(void* const* d_in, const int* in_sizes, int n_in,
                              void* d_out, int out_size) {
    const float* X     = (const float*)d_in[0];
    const float* Adj   = (const float*)d_in[1];
    const int*   edges = (const int*)d_in[2];
    const int*   smask = (const int*)d_in[3];
    const float* W1    = (const float*)d_in[4];
    const float* b1    = (const float*)d_in[5];
    const float* W2    = (const float*)d_in[6];
    const float* b2    = (const float*)d_in[7];
    const float* Wd    = (const float*)d_in[8];
    const float* bd    = (const float*)d_in[9];
    const float* Wo    = (const float*)d_in[10];
    const float* bo    = (const float*)d_in[11];
    float* out = (float*)d_out;

    __half *ah, *bt, *h16, *wdt;
    float *tmp, *h, *part;
    cudaGetSymbolAddress((void**)&ah, g_ah);
    cudaGetSymbolAddress((void**)&bt, g_bt);
    cudaGetSymbolAddress((void**)&h16, g_h16);
    cudaGetSymbolAddress((void**)&wdt, g_wdt);
    cudaGetSymbolAddress((void**)&tmp, g_tmp);
    cudaGetSymbolAddress((void**)&h, g_h);
    cudaGetSymbolAddress((void**)&part, g_part);

    cudaFuncSetAttribute(adj_mma_h, cudaFuncAttributeMaxDynamicSharedMemorySize, SMEM_ADJ);
    cudaFuncSetAttribute(edge_mma_h, cudaFuncAttributeMaxDynamicSharedMemorySize, SMEM_EDGE);

    dim3 tb(32, 8);
    dim3 agrid(NNODES / 128, KSPLIT);
    const int rgrid = (NNODES * HID / 4) / 256;

    convert_a<<<8192, 256>>>(Adj, ah);
    transpose_h<2 * HID, UNITS><<<dim3(4, 8), tb>>>(Wd, wdt);

    // layer 1
    gemm_n64<<<NNODES / 128, 256>>>(X, W1, tmp, 128);
    transpose_h<NNODES, HID><<<dim3(NNODES / 32, 2), tb>>>(tmp, bt);
    adj_mma_h<<<agrid, 256, SMEM_ADJ>>>(ah, bt, part);
    reduce_sigmoid_f<<<rgrid, 256>>>(part, b1, h);
    // layer 2
    gemm_n64<<<NNODES / 128, 256>>>(h, W2, tmp, 64);
    transpose_h<NNODES, HID><<<dim3(NNODES / 32, 2), tb>>>(tmp, bt);
    adj_mma_h<<<agrid, 256, SMEM_ADJ>>>(ah, bt, part);
    reduce_sigmoid_h<<<rgrid, 256>>>(part, b2, h16);
    // fused edge MLP (fp16 tensor cores)
    edge_mma_h<<<NEDGES / 128, 512, SMEM_EDGE>>>(h16, edges, smask, wdt, bd, Wo, bo, out);
}